// round 5
// baseline (speedup 1.0000x reference)
#include <cuda_runtime.h>

// CumulantSOAP: per-column mean/var of X (200000 x 576 f32) -> (cum - mu) @ W (1728x4) -> 4 floats.
// Single pass (S1, S2); mom1 treated as 0 (pure fp rounding residual). Deterministic.
//
// R5: stage-2 rebuilt — thread=column-group, loop=block ⇒ every partial-reduce load is a
// coalesced 2304B row burst (R4's lane=b mapping caused 32 sectors/LDG, 14.4us).
// K2a (74 blocks) + fused last-block finish. K1: launch_bounds(288,6) for 54 warps/SM.

#define NROWS   200000
#define PCOLS   576
#define PV      144                       // float4 groups per row
#define TOTALV  ((size_t)NROWS * PV)      // 28,800,000 float4
#define BLK1    288
#define G1      740
#define B2      74
#define CHUNK   10                        // G1 / B2

__device__ float g_s1[(size_t)G1 * PCOLS];   // [block][col] partial sum x
__device__ float g_s2[(size_t)G1 * PCOLS];   // [block][col] partial sum x^2
__device__ float g_t1[(size_t)B2 * PCOLS];   // [k2block][col]
__device__ float g_t2[(size_t)B2 * PCOLS];
__device__ int   g_count = 0;

// -------------------- Stage 1 --------------------
__global__ __launch_bounds__(BLK1, 6) void k1_colsums(const float* __restrict__ X) {
    const float4* __restrict__ Xv = reinterpret_cast<const float4*>(X);
    const int tid = threadIdx.x;

    float s1x = 0.f, s1y = 0.f, s1z = 0.f, s1w = 0.f;
    float s2x = 0.f, s2y = 0.f, s2z = 0.f, s2w = 0.f;

    size_t i = (size_t)blockIdx.x * BLK1 + tid;
    const size_t stride = (size_t)G1 * BLK1;   // 213120, divisible by 144

    for (; i + 3 * stride < TOTALV; i += 4 * stride) {
        float4 a = __ldcs(Xv + i);
        float4 b = __ldcs(Xv + i + stride);
        float4 c = __ldcs(Xv + i + 2 * stride);
        float4 d = __ldcs(Xv + i + 3 * stride);

        s1x += a.x; s1y += a.y; s1z += a.z; s1w += a.w;
        s2x = fmaf(a.x, a.x, s2x); s2y = fmaf(a.y, a.y, s2y);
        s2z = fmaf(a.z, a.z, s2z); s2w = fmaf(a.w, a.w, s2w);

        s1x += b.x; s1y += b.y; s1z += b.z; s1w += b.w;
        s2x = fmaf(b.x, b.x, s2x); s2y = fmaf(b.y, b.y, s2y);
        s2z = fmaf(b.z, b.z, s2z); s2w = fmaf(b.w, b.w, s2w);

        s1x += c.x; s1y += c.y; s1z += c.z; s1w += c.w;
        s2x = fmaf(c.x, c.x, s2x); s2y = fmaf(c.y, c.y, s2y);
        s2z = fmaf(c.z, c.z, s2z); s2w = fmaf(c.w, c.w, s2w);

        s1x += d.x; s1y += d.y; s1z += d.z; s1w += d.w;
        s2x = fmaf(d.x, d.x, s2x); s2y = fmaf(d.y, d.y, s2y);
        s2z = fmaf(d.z, d.z, s2z); s2w = fmaf(d.w, d.w, s2w);
    }
    for (; i < TOTALV; i += stride) {
        float4 a = __ldcs(Xv + i);
        s1x += a.x; s1y += a.y; s1z += a.z; s1w += a.w;
        s2x = fmaf(a.x, a.x, s2x); s2y = fmaf(a.y, a.y, s2y);
        s2z = fmaf(a.z, a.z, s2z); s2w = fmaf(a.w, a.w, s2w);
    }

    // pair-reduce: tid and tid+144 share the same column group (tid % 144)
    __shared__ float red[PV][8];
    if (tid >= PV) {
        float* r = red[tid - PV];
        r[0] = s1x; r[1] = s1y; r[2] = s1z; r[3] = s1w;
        r[4] = s2x; r[5] = s2y; r[6] = s2z; r[7] = s2w;
    }
    __syncthreads();
    if (tid < PV) {
        const float* r = red[tid];
        float4 o1 = make_float4(s1x + r[0], s1y + r[1], s1z + r[2], s1w + r[3]);
        float4 o2 = make_float4(s2x + r[4], s2y + r[5], s2z + r[6], s2w + r[7]);
        float4* d1 = reinterpret_cast<float4*>(g_s1) + (size_t)blockIdx.x * PV + tid;
        float4* d2 = reinterpret_cast<float4*>(g_s2) + (size_t)blockIdx.x * PV + tid;
        *d1 = o1;
        *d2 = o2;
    }
}

// -------- Stage 2: coalesced partial reduce + fused last-block projection --------
__global__ __launch_bounds__(PV) void k2_project(const float* __restrict__ mu,
                                                 const float* __restrict__ W,
                                                 float* __restrict__ out) {
    const int g = threadIdx.x;               // float4 column group 0..143
    const float4* __restrict__ s1v = reinterpret_cast<const float4*>(g_s1);
    const float4* __restrict__ s2v = reinterpret_cast<const float4*>(g_s2);

    float4 t1 = make_float4(0.f, 0.f, 0.f, 0.f);
    float4 t2 = make_float4(0.f, 0.f, 0.f, 0.f);
    const int b0 = blockIdx.x * CHUNK;
    #pragma unroll
    for (int b = b0; b < b0 + CHUNK; b++) {
        float4 a = __ldg(s1v + (size_t)b * PV + g);
        float4 c = __ldg(s2v + (size_t)b * PV + g);
        t1.x += a.x; t1.y += a.y; t1.z += a.z; t1.w += a.w;
        t2.x += c.x; t2.y += c.y; t2.z += c.z; t2.w += c.w;
    }
    reinterpret_cast<float4*>(g_t1)[(size_t)blockIdx.x * PV + g] = t1;
    reinterpret_cast<float4*>(g_t2)[(size_t)blockIdx.x * PV + g] = t2;

    __threadfence();
    __syncthreads();
    __shared__ int s_last;
    if (g == 0) s_last = (atomicAdd(&g_count, 1) == B2 - 1);
    __syncthreads();
    if (!s_last) return;

    // ---- final block: reduce 74 rows, compute cumulants, fold projection ----
    const float4* __restrict__ t1v = reinterpret_cast<const float4*>(g_t1);
    const float4* __restrict__ t2v = reinterpret_cast<const float4*>(g_t2);
    float4 u1 = make_float4(0.f, 0.f, 0.f, 0.f);
    float4 u2 = make_float4(0.f, 0.f, 0.f, 0.f);
    #pragma unroll 2
    for (int b = 0; b < B2; b++) {
        float4 a = __ldcv(t1v + (size_t)b * PV + g);   // bypass L1: fresh from L2
        float4 c = __ldcv(t2v + (size_t)b * PV + g);
        u1.x += a.x; u1.y += a.y; u1.z += a.z; u1.w += a.w;
        u2.x += c.x; u2.y += c.y; u2.z += c.z; u2.w += c.w;
    }

    const float invN = 1.0f / (float)NROWS;
    float acc[4] = {0.f, 0.f, 0.f, 0.f};
    float s1c[4] = {u1.x, u1.y, u1.z, u1.w};
    float s2c[4] = {u2.x, u2.y, u2.z, u2.w};
    #pragma unroll
    for (int c = 0; c < 4; c++) {
        int col  = 4 * g + c;
        int base = 3 * col;
        float m    = s1c[c] * invN;
        float mom2 = fmaf(-m, m, s2c[c] * invN);   // E[x^2] - m^2
        float c0 = m    - __ldg(mu + base);
        float c1 =      - __ldg(mu + base + 1);    // mom1 ~ 0
        float c2 = mom2 - __ldg(mu + base + 2);
        #pragma unroll
        for (int k = 0; k < 4; k++) {
            float w0 = __ldg(W + (base    ) * 4 + k);
            float w1 = __ldg(W + (base + 1) * 4 + k);
            float w2 = __ldg(W + (base + 2) * 4 + k);
            acc[k] = fmaf(c0, w0, fmaf(c1, w1, fmaf(c2, w2, acc[k])));
        }
    }

    __shared__ float sred[PV][4];
    #pragma unroll
    for (int k = 0; k < 4; k++) sred[g][k] = acc[k];
    __syncthreads();
    // tree reduce over 144 threads
    if (g < 64) {
        #pragma unroll
        for (int k = 0; k < 4; k++) {
            float v = sred[g][k] + sred[g + 64][k];
            if (g < 16) v += sred[g + 128][k];
            sred[g][k] = v;
        }
    }
    __syncthreads();
    if (g < 32) {
        #pragma unroll
        for (int k = 0; k < 4; k++) sred[g][k] += sred[g + 32][k];
    }
    __syncthreads();
    if (g < 4) {
        float v = 0.f;
        #pragma unroll
        for (int j = 0; j < 32; j++) v += sred[j][g];
        out[g] = v;
    }
    if (g == 0) g_count = 0;   // reset for next graph replay
}

extern "C" void kernel_launch(void* const* d_in, const int* in_sizes, int n_in,
                              void* d_out, int out_size) {
    const float* X  = (const float*)d_in[0];
    const float* mu = (const float*)d_in[1];
    const float* W  = (const float*)d_in[2];
    float* out = (float*)d_out;

    k1_colsums<<<G1, BLK1>>>(X);
    k2_project<<<B2, PV>>>(mu, W, out);
}